// round 7
// baseline (speedup 1.0000x reference)
#include <cuda_runtime.h>
#include <math.h>

#define T_LEN 128
#define B_DIM 128
#define I_DIM 128
#define H_DIM 512
#define W_WIN 16
#define G4H   2048   // 4*H
#define IH    640    // I+H
#define KC_K  1152   // I + H + H (virtual K for cell GEMM)

// ---------------- scratch (device globals; no allocation allowed) ----------
__device__ float g_c[B_DIM * H_DIM];               // cell state fp32
__device__ float g_V[W_WIN * B_DIM * H_DIM];       // V cache fp32
__device__ float g_Q[B_DIM * H_DIM];               // Q fp32

// tf32-split activations (hi/lo), maintained by epilogues
__device__ float g_h_hi[2][B_DIM * H_DIM];
__device__ float g_h_lo[2][B_DIM * H_DIM];
__device__ float g_c_hi[B_DIM * H_DIM];
__device__ float g_c_lo[B_DIM * H_DIM];
__device__ float g_attn_hi[B_DIM * H_DIM];
__device__ float g_attn_lo[B_DIM * H_DIM];
__device__ float g_x_hi[T_LEN * B_DIM * I_DIM];
__device__ float g_x_lo[T_LEN * B_DIM * I_DIM];

// transposed + tf32-split weights (computed once per call)
__device__ float g_Wc_hi[G4H * KC_K];   // [n=2048][k=1152]  (Wi|Wh|Wa)
__device__ float g_Wc_lo[G4H * KC_K];
__device__ float g_Wq_hi[H_DIM * IH];   // [n=512][k=640]
__device__ float g_Wq_lo[H_DIM * IH];
__device__ float g_Wv_hi[H_DIM * H_DIM];// [n=512][k=512]
__device__ float g_Wv_lo[H_DIM * H_DIM];

// ---------------- helpers ---------------------------------------------------
__device__ __forceinline__ unsigned smem_u32(const void* p) {
    return (unsigned)__cvta_generic_to_shared(p);
}
__device__ __forceinline__ void cp16(void* dst, const void* src) {
    asm volatile("cp.async.cg.shared.global [%0], [%1], 16;\n"
                 :: "r"(smem_u32(dst)), "l"(src));
}
__device__ __forceinline__ void cp_commit() {
    asm volatile("cp.async.commit_group;\n" ::: "memory");
}
__device__ __forceinline__ void cp_wait1() {
    asm volatile("cp.async.wait_group 1;\n" ::: "memory");
}
__device__ __forceinline__ void cp_wait0() {
    asm volatile("cp.async.wait_group 0;\n" ::: "memory");
}
__device__ __forceinline__ unsigned tf32u(float a) {
    unsigned r; asm("cvt.rna.tf32.f32 %0, %1;" : "=r"(r) : "f"(a)); return r;
}
// D += A(m16k8,row) * B(k8n8,col)   tf32
__device__ __forceinline__ void mma8(float* c, const unsigned* a,
                                     unsigned b0, unsigned b1) {
    asm("mma.sync.aligned.m16n8k8.row.col.f32.tf32.tf32.f32 "
        "{%0,%1,%2,%3},{%4,%5,%6,%7},{%8,%9},{%0,%1,%2,%3};"
        : "+f"(c[0]), "+f"(c[1]), "+f"(c[2]), "+f"(c[3])
        : "r"(a[0]), "r"(a[1]), "r"(a[2]), "r"(a[3]), "r"(b0), "r"(b1));
}
__device__ __forceinline__ void split_store(float v, float* hi, float* lo) {
    float h = __uint_as_float(tf32u(v));
    *hi = h;
    *lo = __uint_as_float(tf32u(v - h));
}

// ---------------- init: h=0, c=0 (and splits), V[w][b][:] = bv --------------
__global__ void init_kernel(const float* __restrict__ bv) {
    int idx = blockIdx.x * blockDim.x + threadIdx.x;
    int stride = gridDim.x * blockDim.x;
    for (int i = idx; i < B_DIM * H_DIM; i += stride) {
        g_h_hi[0][i] = 0.f; g_h_lo[0][i] = 0.f;
        g_c[i] = 0.f; g_c_hi[i] = 0.f; g_c_lo[i] = 0.f;
    }
    for (int i = idx; i < W_WIN * B_DIM * H_DIM; i += stride) {
        g_V[i] = bv[i % H_DIM];
    }
}

// ---------------- prep kernels ----------------------------------------------
__global__ void prep_x(const float* __restrict__ x) {
    long total = (long)T_LEN * B_DIM * I_DIM;
    long stride = (long)gridDim.x * blockDim.x;
    for (long i = (long)blockIdx.x * blockDim.x + threadIdx.x; i < total; i += stride) {
        split_store(x[i], &g_x_hi[i], &g_x_lo[i]);
    }
}
__global__ void prep_wc(const float* __restrict__ Wi,
                        const float* __restrict__ Wh,
                        const float* __restrict__ Wa) {
    long total = (long)G4H * KC_K;
    long stride = (long)gridDim.x * blockDim.x;
    for (long i = (long)blockIdx.x * blockDim.x + threadIdx.x; i < total; i += stride) {
        int n = (int)(i / KC_K), k = (int)(i % KC_K);
        float w;
        if (k < I_DIM)   w = Wi[(size_t)k * G4H + n];
        else if (k < IH) w = Wh[(size_t)(k - I_DIM) * G4H + n];
        else             w = Wa[(size_t)(k - IH) * G4H + n];
        split_store(w, &g_Wc_hi[i], &g_Wc_lo[i]);
    }
}
__global__ void prep_wqv(const float* __restrict__ Wq,
                         const float* __restrict__ Wv) {
    long totq = (long)H_DIM * IH;
    long totv = (long)H_DIM * H_DIM;
    long stride = (long)gridDim.x * blockDim.x;
    for (long i = (long)blockIdx.x * blockDim.x + threadIdx.x; i < totq + totv; i += stride) {
        if (i < totq) {
            int n = (int)(i / IH), k = (int)(i % IH);
            split_store(Wq[(size_t)k * H_DIM + n], &g_Wq_hi[i], &g_Wq_lo[i]);
        } else {
            long j = i - totq;
            int n = (int)(j / H_DIM), k = (int)(j % H_DIM);
            split_store(Wv[(size_t)k * H_DIM + n], &g_Wv_hi[j], &g_Wv_lo[j]);
        }
    }
}

// ---------------- KA: Q = [x_t|h] @ Wq + bq   AND   V[t%W] = c @ Wv + bv ----
// grid = 256 blocks x 128 threads (4 warps).
// Blocks 0..127 : Q-GEMM (M=128,N=512,K=640)  tile M16 x N32, warp m16n8
// Blocks 128..255: V-GEMM (M=128,N=512,K=512)
// A pre-split hi/lo; zero cvt in mainloop; 3 independent mma chains.
__global__ __launch_bounds__(128) void ka_kernel(
    int t, const float* __restrict__ bq, const float* __restrict__ bv)
{
    __shared__ float Ah[2][16][36], Al[2][16][36];
    __shared__ float Bh[2][32][36], Bl[2][32][36];

    const int blk = blockIdx.x;
    const bool isQ = (blk < 128);
    const int bid = blk & 127;
    const int m0 = (bid >> 4) * 16;     // 8 M-tiles
    const int n0 = (bid & 15) * 32;     // 16 N-tiles

    const float* __restrict__ xhi = g_x_hi + (size_t)t * B_DIM * I_DIM;
    const float* __restrict__ xlo = g_x_lo + (size_t)t * B_DIM * I_DIM;
    const float* __restrict__ hhi = g_h_hi[t & 1];
    const float* __restrict__ hlo = g_h_lo[t & 1];
    const float* __restrict__ WH  = isQ ? g_Wq_hi : g_Wv_hi;
    const float* __restrict__ WL  = isQ ? g_Wq_lo : g_Wv_lo;
    const int Ktot = isQ ? IH : H_DIM;
    const int nt   = Ktot / 32;

    const int tid  = threadIdx.x;
    const int lane = tid & 31;
    const int warp = tid >> 5;
    const int g    = lane >> 2, tg = lane & 3;

    const int ar  = tid >> 3;            // 0..15 row (A chunks)
    const int ac4 = (tid & 7) * 4;

    auto issue = [&](int it, int s) {
        const int kk = it * 32;
        // A hi/lo: 16 rows x 32 k -> 1 cp16/thread each
        {
            const float *ph, *pl;
            if (isQ) {
                int gk = kk + ac4;
                if (gk < I_DIM) {
                    ph = xhi + (size_t)(m0 + ar) * I_DIM + gk;
                    pl = xlo + (size_t)(m0 + ar) * I_DIM + gk;
                } else {
                    ph = hhi + (size_t)(m0 + ar) * H_DIM + (gk - I_DIM);
                    pl = hlo + (size_t)(m0 + ar) * H_DIM + (gk - I_DIM);
                }
            } else {
                ph = g_c_hi + (size_t)(m0 + ar) * H_DIM + kk + ac4;
                pl = g_c_lo + (size_t)(m0 + ar) * H_DIM + kk + ac4;
            }
            cp16(&Ah[s][ar][ac4], ph);
            cp16(&Al[s][ar][ac4], pl);
        }
        // B hi/lo: 32 n-rows x 32 k -> 2 cp16/thread each
        #pragma unroll
        for (int l = 0; l < 2; l++) {
            int id = tid + l * 128;
            int r = id >> 3, c4 = (id & 7) * 4;
            size_t off = (size_t)(n0 + r) * Ktot + kk + c4;
            cp16(&Bh[s][r][c4], WH + off);
            cp16(&Bl[s][r][c4], WL + off);
        }
        cp_commit();
    };

    float cHH[4] = {}, cLH[4] = {}, cHL[4] = {};

    issue(0, 0);
    for (int it = 0; it < nt; it++) {
        const int s = it & 1;
        if (it + 1 < nt) { issue(it + 1, s ^ 1); cp_wait1(); }
        else             { cp_wait0(); }
        __syncthreads();

        #pragma unroll
        for (int k8 = 0; k8 < 4; k8++) {
            const int k0 = k8 * 8;
            unsigned ah[4], al[4];
            ah[0] = __float_as_uint(Ah[s][g][k0 + tg]);
            ah[1] = __float_as_uint(Ah[s][g + 8][k0 + tg]);
            ah[2] = __float_as_uint(Ah[s][g][k0 + tg + 4]);
            ah[3] = __float_as_uint(Ah[s][g + 8][k0 + tg + 4]);
            al[0] = __float_as_uint(Al[s][g][k0 + tg]);
            al[1] = __float_as_uint(Al[s][g + 8][k0 + tg]);
            al[2] = __float_as_uint(Al[s][g][k0 + tg + 4]);
            al[3] = __float_as_uint(Al[s][g + 8][k0 + tg + 4]);

            int n = warp * 8 + g;
            unsigned bh0 = __float_as_uint(Bh[s][n][k0 + tg]);
            unsigned bh1 = __float_as_uint(Bh[s][n][k0 + tg + 4]);
            unsigned bl0 = __float_as_uint(Bl[s][n][k0 + tg]);
            unsigned bl1 = __float_as_uint(Bl[s][n][k0 + tg + 4]);
            mma8(cHH, ah, bh0, bh1);
            mma8(cLH, al, bh0, bh1);
            mma8(cHL, ah, bl0, bl1);
        }
        __syncthreads();
    }

    float acc[4];
    #pragma unroll
    for (int i = 0; i < 4; i++) acc[i] = cHH[i] + cLH[i] + cHL[i];

    const float* bias = isQ ? bq : bv;
    float* outp = isQ ? g_Q : (g_V + (size_t)(t % W_WIN) * B_DIM * H_DIM);
    int col = n0 + warp * 8 + 2 * tg;
    int r0 = m0 + g, r1 = m0 + g + 8;
    outp[(size_t)r0 * H_DIM + col]     = acc[0] + bias[col];
    outp[(size_t)r0 * H_DIM + col + 1] = acc[1] + bias[col + 1];
    outp[(size_t)r1 * H_DIM + col]     = acc[2] + bias[col];
    outp[(size_t)r1 * H_DIM + col + 1] = acc[3] + bias[col + 1];
}

// ---------------- KB: scores -> softmax -> attn (writes attn splits) --------
__global__ __launch_bounds__(128) void kb_kernel(int t) {
    const float inv_sqrt_dk = 0.044194173824159216f; // 1/sqrt(512)
    int b = blockIdx.x;
    int tid = threadIdx.x;
    __shared__ float sQ[H_DIM];
    __shared__ float sS[W_WIN];
    __shared__ float sP[W_WIN];

    for (int j = tid; j < H_DIM; j += 128) sQ[j] = g_Q[(size_t)b * H_DIM + j];
    __syncthreads();

    int nv = (t + 1 < W_WIN) ? (t + 1) : W_WIN;
    int warp = tid / 32, lane = tid % 32;
    for (int w = warp; w < nv; w += 4) {
        const float* Vp = g_V + (size_t)(w * B_DIM + b) * H_DIM;
        float p = 0.f;
        for (int j = lane; j < H_DIM; j += 32) p += sQ[j] * Vp[j];
        #pragma unroll
        for (int o = 16; o > 0; o >>= 1) p += __shfl_xor_sync(0xffffffffu, p, o);
        if (lane == 0) sS[w] = p * inv_sqrt_dk;
    }
    __syncthreads();
    if (tid == 0) {
        float m = sS[0];
        for (int w = 1; w < nv; w++) m = fmaxf(m, sS[w]);
        float sum = 0.f;
        for (int w = 0; w < nv; w++) { float e = expf(sS[w] - m); sP[w] = e; sum += e; }
        float inv = 1.f / sum;
        for (int w = 0; w < nv; w++) sP[w] *= inv;
    }
    __syncthreads();
    for (int j = tid; j < H_DIM; j += 128) {
        float a = 0.f;
        for (int w = 0; w < nv; w++)
            a += sP[w] * g_V[(size_t)(w * B_DIM + b) * H_DIM + j];
        size_t idx = (size_t)b * H_DIM + j;
        split_store(a, &g_attn_hi[idx], &g_attn_lo[idx]);
    }
}

// ---------------- KC: fused cell GEMM (tf32 mma) + LSTM pointwise -----------
// preact = [x|h|attn] @ Wc + biases, virtual K=1152.
// grid = 512 blocks (8 M-tiles x 64 j-tiles) x 128 threads.
// Tile: M=16 x N=32 (4 gates x 8 j). Warp w computes gate w (m16n8).
__global__ __launch_bounds__(128) void kc_kernel(
    int t,
    const float* __restrict__ bi, const float* __restrict__ ba,
    float* __restrict__ out)
{
    __shared__ float Ah[2][16][36], Al[2][16][36];
    __shared__ float Bh[2][32][36], Bl[2][32][36];
    __shared__ float sG[4][16][9];   // [gate][row][j] preact exchange

    const int m0 = (blockIdx.x >> 6) * 16;  // 8 M-tiles
    const int j0 = (blockIdx.x & 63) * 8;   // 64 j-tiles

    const float* __restrict__ xhi = g_x_hi + (size_t)t * B_DIM * I_DIM;
    const float* __restrict__ xlo = g_x_lo + (size_t)t * B_DIM * I_DIM;
    const float* __restrict__ hhi = g_h_hi[t & 1];
    const float* __restrict__ hlo = g_h_lo[t & 1];
    float* __restrict__ hohi = g_h_hi[(t + 1) & 1];
    float* __restrict__ holo = g_h_lo[(t + 1) & 1];

    const int tid  = threadIdx.x;
    const int lane = tid & 31;
    const int warp = tid >> 5;
    const int g    = lane >> 2, tg = lane & 3;

    const int ar  = tid >> 3;
    const int ac4 = (tid & 7) * 4;

    auto issue = [&](int it, int s) {
        const int kk = it * 32;
        const float *ph, *pl;
        {
            int gk = kk + ac4;
            if (gk < I_DIM) {
                ph = xhi + (size_t)(m0 + ar) * I_DIM + gk;
                pl = xlo + (size_t)(m0 + ar) * I_DIM + gk;
            } else if (gk < IH) {
                ph = hhi + (size_t)(m0 + ar) * H_DIM + (gk - I_DIM);
                pl = hlo + (size_t)(m0 + ar) * H_DIM + (gk - I_DIM);
            } else {
                ph = g_attn_hi + (size_t)(m0 + ar) * H_DIM + (gk - IH);
                pl = g_attn_lo + (size_t)(m0 + ar) * H_DIM + (gk - IH);
            }
            cp16(&Ah[s][ar][ac4], ph);
            cp16(&Al[s][ar][ac4], pl);
        }
        #pragma unroll
        for (int l = 0; l < 2; l++) {
            int id = tid + l * 128;
            int r = id >> 3, c4 = (id & 7) * 4;
            int gn = (r >> 3) * H_DIM + j0 + (r & 7);
            size_t off = (size_t)gn * KC_K + kk + c4;
            cp16(&Bh[s][r][c4], g_Wc_hi + off);
            cp16(&Bl[s][r][c4], g_Wc_lo + off);
        }
        cp_commit();
    };

    float cHH[4] = {}, cLH[4] = {}, cHL[4] = {};

    const int nt = KC_K / 32;  // 36
    issue(0, 0);
    for (int it = 0; it < nt; it++) {
        const int s = it & 1;
        if (it + 1 < nt) { issue(it + 1, s ^ 1); cp_wait1(); }
        else             { cp_wait0(); }
        __syncthreads();

        #pragma unroll
        for (int k8 = 0; k8 < 4; k8++) {
            const int k0 = k8 * 8;
            unsigned ah[4], al[4];
            ah[0] = __float_as_uint(Ah[s][g][k0 + tg]);
            ah[1] = __float_as_uint(Ah[s][g + 8][k0 + tg]);
            ah[2] = __float_as_uint(Ah[s][g][k0 + tg + 4]);
            ah[3] = __float_as_uint(Ah[s][g + 8][k0 + tg + 4]);
            al[0] = __float_as_uint(Al[s][g][k0 + tg]);
            al[1] = __float_as_uint(Al[s][g + 8][k0 + tg]);
            al[2] = __float_as_uint(Al[s][g][k0 + tg + 4]);
            al[3] = __float_as_uint(Al[s][g + 8][k0 + tg + 4]);

            int n = warp * 8 + g;   // warp w -> gate w, n-row = gate*8 + g
            unsigned bh0 = __float_as_uint(Bh[s][n][k0 + tg]);
            unsigned bh1 = __float_as_uint(Bh[s][n][k0 + tg + 4]);
            unsigned bl0 = __float_as_uint(Bl[s][n][k0 + tg]);
            unsigned bl1 = __float_as_uint(Bl[s][n][k0 + tg + 4]);
            mma8(cHH, ah, bh0, bh1);
            mma8(cLH, al, bh0, bh1);
            mma8(cHL, ah, bl0, bl1);
        }
        __syncthreads();
    }

    // exchange preact through smem: warp w holds gate w, m16 x j8
    {
        float v0 = cHH[0] + cLH[0] + cHL[0];
        float v1 = cHH[1] + cLH[1] + cHL[1];
        float v2 = cHH[2] + cLH[2] + cHL[2];
        float v3 = cHH[3] + cLH[3] + cHL[3];
        sG[warp][g][2 * tg]         = v0;
        sG[warp][g][2 * tg + 1]     = v1;
        sG[warp][g + 8][2 * tg]     = v2;
        sG[warp][g + 8][2 * tg + 1] = v3;
    }
    __syncthreads();

    // pointwise: 1 cell per thread
    const int row = tid >> 3;          // 0..15
    const int jj  = tid & 7;           // 0..7
    const int j   = j0 + jj;
    const int b   = m0 + row;

    float pi = sG[0][row][jj] + bi[j]             + ba[j];
    float pf = sG[1][row][jj] + bi[H_DIM + j]     + ba[H_DIM + j];
    float po = sG[2][row][jj] + bi[2 * H_DIM + j] + ba[2 * H_DIM + j];
    float pg = sG[3][row][jj] + bi[3 * H_DIM + j] + ba[3 * H_DIM + j];

    float ig = 1.f / (1.f + expf(-pi));
    float fg = 1.f / (1.f + expf(-pf));
    float og = 1.f / (1.f + expf(-po));
    float gg = tanhf(pg);

    size_t idx = (size_t)b * H_DIM + j;
    float cn = g_c[idx] * fg + ig * gg;
    float hn = og * tanhf(cn);

    g_c[idx] = cn;
    split_store(cn, &g_c_hi[idx], &g_c_lo[idx]);
    split_store(hn, &hohi[idx], &holo[idx]);
    out[(size_t)t * B_DIM * H_DIM + idx] = hn;
}

// ---------------- launcher --------------------------------------------------
extern "C" void kernel_launch(void* const* d_in, const int* in_sizes, int n_in,
                              void* d_out, int out_size) {
    const float* x  = (const float*)d_in[0];
    const float* Wi = (const float*)d_in[1];
    const float* bi = (const float*)d_in[2];
    const float* Wh = (const float*)d_in[3];
    const float* Wv = (const float*)d_in[4];
    const float* bv = (const float*)d_in[5];
    const float* Wq = (const float*)d_in[6];
    const float* bq = (const float*)d_in[7];
    const float* Wa = (const float*)d_in[8];
    const float* ba = (const float*)d_in[9];
    float* out = (float*)d_out;

    init_kernel<<<1024, 256>>>(bv);
    prep_x<<<2048, 256>>>(x);
    prep_wc<<<2048, 256>>>(Wi, Wh, Wa);
    prep_wqv<<<1024, 256>>>(Wq, Wv);
    for (int t = 0; t < T_LEN; t++) {
        ka_kernel<<<256, 128>>>(t, bq, bv);
        kb_kernel<<<128, 128>>>(t);
        kc_kernel<<<512, 128>>>(t, bi, ba, out);
    }
}

// round 8
// speedup vs baseline: 1.1385x; 1.1385x over previous
#include <cuda_runtime.h>
#include <math.h>

#define T_LEN 128
#define B_DIM 128
#define I_DIM 128
#define H_DIM 512
#define W_WIN 16
#define G4H   2048   // 4*H
#define IH    640    // I+H
#define KC_K  1152   // I + H + H (virtual K for cell GEMM)

// ---------------- scratch (device globals; no allocation allowed) ----------
__device__ float g_c[B_DIM * H_DIM];               // cell state fp32
__device__ float g_V[W_WIN * B_DIM * H_DIM];       // V cache fp32
__device__ float g_Q[B_DIM * H_DIM];               // Q fp32

// tf32-split activations (hi/lo), maintained by epilogues
__device__ float g_h_hi[2][B_DIM * H_DIM];
__device__ float g_h_lo[2][B_DIM * H_DIM];
__device__ float g_c_hi[B_DIM * H_DIM];
__device__ float g_c_lo[B_DIM * H_DIM];
__device__ float g_attn_hi[B_DIM * H_DIM];
__device__ float g_attn_lo[B_DIM * H_DIM];
__device__ float g_x_hi[T_LEN * B_DIM * I_DIM];
__device__ float g_x_lo[T_LEN * B_DIM * I_DIM];

// transposed + tf32-split weights (computed once per call)
__device__ float g_Wc_hi[G4H * KC_K];   // [n=2048][k=1152]  (Wi|Wh|Wa)
__device__ float g_Wc_lo[G4H * KC_K];
__device__ float g_Wq_hi[H_DIM * IH];   // [n=512][k=640]
__device__ float g_Wq_lo[H_DIM * IH];
__device__ float g_Wv_hi[H_DIM * H_DIM];// [n=512][k=512]
__device__ float g_Wv_lo[H_DIM * H_DIM];

// ---------------- helpers ---------------------------------------------------
__device__ __forceinline__ unsigned smem_u32(const void* p) {
    return (unsigned)__cvta_generic_to_shared(p);
}
__device__ __forceinline__ void cp16(void* dst, const void* src) {
    asm volatile("cp.async.cg.shared.global [%0], [%1], 16;\n"
                 :: "r"(smem_u32(dst)), "l"(src));
}
__device__ __forceinline__ void cp_commit() {
    asm volatile("cp.async.commit_group;\n" ::: "memory");
}
__device__ __forceinline__ void cp_wait1() {
    asm volatile("cp.async.wait_group 1;\n" ::: "memory");
}
__device__ __forceinline__ void cp_wait0() {
    asm volatile("cp.async.wait_group 0;\n" ::: "memory");
}
__device__ __forceinline__ unsigned tf32u(float a) {
    unsigned r; asm("cvt.rna.tf32.f32 %0, %1;" : "=r"(r) : "f"(a)); return r;
}
// D += A(m16k8,row) * B(k8n8,col)   tf32
__device__ __forceinline__ void mma8(float* c, const unsigned* a,
                                     unsigned b0, unsigned b1) {
    asm("mma.sync.aligned.m16n8k8.row.col.f32.tf32.tf32.f32 "
        "{%0,%1,%2,%3},{%4,%5,%6,%7},{%8,%9},{%0,%1,%2,%3};"
        : "+f"(c[0]), "+f"(c[1]), "+f"(c[2]), "+f"(c[3])
        : "r"(a[0]), "r"(a[1]), "r"(a[2]), "r"(a[3]), "r"(b0), "r"(b1));
}
__device__ __forceinline__ void split_store(float v, float* hi, float* lo) {
    float h = __uint_as_float(tf32u(v));
    *hi = h;
    *lo = __uint_as_float(tf32u(v - h));
}

// ---------------- init: h=0, c=0 (and splits), V[w][b][:] = bv --------------
__global__ void init_kernel(const float* __restrict__ bv) {
    int idx = blockIdx.x * blockDim.x + threadIdx.x;
    int stride = gridDim.x * blockDim.x;
    for (int i = idx; i < B_DIM * H_DIM; i += stride) {
        g_h_hi[0][i] = 0.f; g_h_lo[0][i] = 0.f;
        g_c[i] = 0.f; g_c_hi[i] = 0.f; g_c_lo[i] = 0.f;
    }
    for (int i = idx; i < W_WIN * B_DIM * H_DIM; i += stride) {
        g_V[i] = bv[i % H_DIM];
    }
}

// ---------------- prep kernels ----------------------------------------------
__global__ void prep_x(const float* __restrict__ x) {
    long total = (long)T_LEN * B_DIM * I_DIM;
    long stride = (long)gridDim.x * blockDim.x;
    for (long i = (long)blockIdx.x * blockDim.x + threadIdx.x; i < total; i += stride) {
        split_store(x[i], &g_x_hi[i], &g_x_lo[i]);
    }
}
__global__ void prep_wc(const float* __restrict__ Wi,
                        const float* __restrict__ Wh,
                        const float* __restrict__ Wa) {
    long total = (long)G4H * KC_K;
    long stride = (long)gridDim.x * blockDim.x;
    for (long i = (long)blockIdx.x * blockDim.x + threadIdx.x; i < total; i += stride) {
        int n = (int)(i / KC_K), k = (int)(i % KC_K);
        float w;
        if (k < I_DIM)   w = Wi[(size_t)k * G4H + n];
        else if (k < IH) w = Wh[(size_t)(k - I_DIM) * G4H + n];
        else             w = Wa[(size_t)(k - IH) * G4H + n];
        split_store(w, &g_Wc_hi[i], &g_Wc_lo[i]);
    }
}
__global__ void prep_wqv(const float* __restrict__ Wq,
                         const float* __restrict__ Wv) {
    long totq = (long)H_DIM * IH;
    long totv = (long)H_DIM * H_DIM;
    long stride = (long)gridDim.x * blockDim.x;
    for (long i = (long)blockIdx.x * blockDim.x + threadIdx.x; i < totq + totv; i += stride) {
        if (i < totq) {
            int n = (int)(i / IH), k = (int)(i % IH);
            split_store(Wq[(size_t)k * H_DIM + n], &g_Wq_hi[i], &g_Wq_lo[i]);
        } else {
            long j = i - totq;
            int n = (int)(j / H_DIM), k = (int)(j % H_DIM);
            split_store(Wv[(size_t)k * H_DIM + n], &g_Wv_hi[j], &g_Wv_lo[j]);
        }
    }
}

// ---------------- KA: Q = [x_t|h] @ Wq + bq   AND   V[t%W] = c @ Wv + bv ----
// grid = 128 blocks x 128 threads (4 warps, 2x2 m16n16 each).
// Blocks 0..63 : Q-GEMM (M=128,N=512,K=640)  tile M32 x N32
// Blocks 64..127: V-GEMM (M=128,N=512,K=512)
__global__ __launch_bounds__(128) void ka_kernel(
    int t, const float* __restrict__ bq, const float* __restrict__ bv)
{
    __shared__ float Ah[2][32][36], Al[2][32][36];
    __shared__ float Bh[2][32][36], Bl[2][32][36];

    const int blk = blockIdx.x;
    const bool isQ = (blk < 64);
    const int bid = blk & 63;
    const int m0 = (bid >> 4) * 32;     // 4 M-tiles
    const int n0 = (bid & 15) * 32;     // 16 N-tiles

    const float* __restrict__ xhi = g_x_hi + (size_t)t * B_DIM * I_DIM;
    const float* __restrict__ xlo = g_x_lo + (size_t)t * B_DIM * I_DIM;
    const float* __restrict__ hhi = g_h_hi[t & 1];
    const float* __restrict__ hlo = g_h_lo[t & 1];
    const float* __restrict__ WH  = isQ ? g_Wq_hi : g_Wv_hi;
    const float* __restrict__ WL  = isQ ? g_Wq_lo : g_Wv_lo;
    const int Ktot = isQ ? IH : H_DIM;
    const int nt   = Ktot / 32;

    const int tid  = threadIdx.x;
    const int lane = tid & 31;
    const int warp = tid >> 5;
    const int mrow = (warp & 1) * 16;
    const int ncol = (warp >> 1) * 16;
    const int g    = lane >> 2, tg = lane & 3;

    auto issue = [&](int it, int s) {
        const int kk = it * 32;
        // A hi/lo: 32 rows x 32 k -> 2 cp16/thread each
        #pragma unroll
        for (int l = 0; l < 2; l++) {
            int id = tid + l * 128;
            int r = id >> 3, c4 = (id & 7) * 4;
            const float *ph, *pl;
            if (isQ) {
                int gk = kk + c4;
                if (gk < I_DIM) {
                    ph = xhi + (size_t)(m0 + r) * I_DIM + gk;
                    pl = xlo + (size_t)(m0 + r) * I_DIM + gk;
                } else {
                    ph = hhi + (size_t)(m0 + r) * H_DIM + (gk - I_DIM);
                    pl = hlo + (size_t)(m0 + r) * H_DIM + (gk - I_DIM);
                }
            } else {
                ph = g_c_hi + (size_t)(m0 + r) * H_DIM + kk + c4;
                pl = g_c_lo + (size_t)(m0 + r) * H_DIM + kk + c4;
            }
            cp16(&Ah[s][r][c4], ph);
            cp16(&Al[s][r][c4], pl);
        }
        // B hi/lo: 32 n-rows x 32 k -> 2 cp16/thread each
        #pragma unroll
        for (int l = 0; l < 2; l++) {
            int id = tid + l * 128;
            int r = id >> 3, c4 = (id & 7) * 4;
            size_t off = (size_t)(n0 + r) * Ktot + kk + c4;
            cp16(&Bh[s][r][c4], WH + off);
            cp16(&Bl[s][r][c4], WL + off);
        }
        cp_commit();
    };

    float cHH[2][4] = {}, cLH[2][4] = {}, cHL[2][4] = {};

    issue(0, 0);
    for (int it = 0; it < nt; it++) {
        const int s = it & 1;
        if (it + 1 < nt) { issue(it + 1, s ^ 1); cp_wait1(); }
        else             { cp_wait0(); }
        __syncthreads();

        #pragma unroll
        for (int k8 = 0; k8 < 4; k8++) {
            const int k0 = k8 * 8;
            unsigned ah[4], al[4];
            ah[0] = __float_as_uint(Ah[s][mrow + g][k0 + tg]);
            ah[1] = __float_as_uint(Ah[s][mrow + g + 8][k0 + tg]);
            ah[2] = __float_as_uint(Ah[s][mrow + g][k0 + tg + 4]);
            ah[3] = __float_as_uint(Ah[s][mrow + g + 8][k0 + tg + 4]);
            al[0] = __float_as_uint(Al[s][mrow + g][k0 + tg]);
            al[1] = __float_as_uint(Al[s][mrow + g + 8][k0 + tg]);
            al[2] = __float_as_uint(Al[s][mrow + g][k0 + tg + 4]);
            al[3] = __float_as_uint(Al[s][mrow + g + 8][k0 + tg + 4]);

            #pragma unroll
            for (int ns = 0; ns < 2; ns++) {
                int n = ncol + ns * 8 + g;
                unsigned bh0 = __float_as_uint(Bh[s][n][k0 + tg]);
                unsigned bh1 = __float_as_uint(Bh[s][n][k0 + tg + 4]);
                unsigned bl0 = __float_as_uint(Bl[s][n][k0 + tg]);
                unsigned bl1 = __float_as_uint(Bl[s][n][k0 + tg + 4]);
                mma8(cHH[ns], ah, bh0, bh1);
                mma8(cLH[ns], al, bh0, bh1);
                mma8(cHL[ns], ah, bl0, bl1);
            }
        }
        __syncthreads();
    }

    const float* bias = isQ ? bq : bv;
    float* outp = isQ ? g_Q : (g_V + (size_t)(t % W_WIN) * B_DIM * H_DIM);
    #pragma unroll
    for (int ns = 0; ns < 2; ns++) {
        float a0 = cHH[ns][0] + cLH[ns][0] + cHL[ns][0];
        float a1 = cHH[ns][1] + cLH[ns][1] + cHL[ns][1];
        float a2 = cHH[ns][2] + cLH[ns][2] + cHL[ns][2];
        float a3 = cHH[ns][3] + cLH[ns][3] + cHL[ns][3];
        int col = n0 + ncol + ns * 8 + 2 * tg;
        int r0 = m0 + mrow + g, r1 = r0 + 8;
        outp[(size_t)r0 * H_DIM + col]     = a0 + bias[col];
        outp[(size_t)r0 * H_DIM + col + 1] = a1 + bias[col + 1];
        outp[(size_t)r1 * H_DIM + col]     = a2 + bias[col];
        outp[(size_t)r1 * H_DIM + col + 1] = a3 + bias[col + 1];
    }
}

// ---------------- KB: scores -> softmax -> attn (writes attn splits) --------
__global__ __launch_bounds__(128) void kb_kernel(int t) {
    const float inv_sqrt_dk = 0.044194173824159216f; // 1/sqrt(512)
    int b = blockIdx.x;
    int tid = threadIdx.x;
    __shared__ float sQ[H_DIM];
    __shared__ float sS[W_WIN];
    __shared__ float sP[W_WIN];

    for (int j = tid; j < H_DIM; j += 128) sQ[j] = g_Q[(size_t)b * H_DIM + j];
    __syncthreads();

    int nv = (t + 1 < W_WIN) ? (t + 1) : W_WIN;
    int warp = tid / 32, lane = tid % 32;
    for (int w = warp; w < nv; w += 4) {
        const float* Vp = g_V + (size_t)(w * B_DIM + b) * H_DIM;
        float p = 0.f;
        for (int j = lane; j < H_DIM; j += 32) p += sQ[j] * Vp[j];
        #pragma unroll
        for (int o = 16; o > 0; o >>= 1) p += __shfl_xor_sync(0xffffffffu, p, o);
        if (lane == 0) sS[w] = p * inv_sqrt_dk;
    }
    __syncthreads();
    if (tid == 0) {
        float m = sS[0];
        for (int w = 1; w < nv; w++) m = fmaxf(m, sS[w]);
        float sum = 0.f;
        for (int w = 0; w < nv; w++) { float e = expf(sS[w] - m); sP[w] = e; sum += e; }
        float inv = 1.f / sum;
        for (int w = 0; w < nv; w++) sP[w] *= inv;
    }
    __syncthreads();
    for (int j = tid; j < H_DIM; j += 128) {
        float a = 0.f;
        for (int w = 0; w < nv; w++)
            a += sP[w] * g_V[(size_t)(w * B_DIM + b) * H_DIM + j];
        size_t idx = (size_t)b * H_DIM + j;
        split_store(a, &g_attn_hi[idx], &g_attn_lo[idx]);
    }
}

// ---------------- KC: fused cell GEMM (tf32 mma) + LSTM pointwise -----------
// preact = [x|h|attn] @ Wc + biases, virtual K=1152.
// grid = 256 blocks (4 M-tiles x 64 j-tiles) x 128 threads.
// Tile: M=32 x N=32 (4 gates x 8 j). Warp 2x2: m16 x n16.
__global__ __launch_bounds__(128) void kc_kernel(
    int t,
    const float* __restrict__ bi, const float* __restrict__ ba,
    float* __restrict__ out)
{
    __shared__ float Ah[2][32][36], Al[2][32][36];
    __shared__ float Bh[2][32][36], Bl[2][32][36];
    __shared__ float sP[32][33];   // [row][col] preact exchange

    const int m0 = (blockIdx.x >> 6) * 32;  // 4 M-tiles
    const int j0 = (blockIdx.x & 63) * 8;   // 64 j-tiles

    const float* __restrict__ xhi = g_x_hi + (size_t)t * B_DIM * I_DIM;
    const float* __restrict__ xlo = g_x_lo + (size_t)t * B_DIM * I_DIM;
    const float* __restrict__ hhi = g_h_hi[t & 1];
    const float* __restrict__ hlo = g_h_lo[t & 1];
    float* __restrict__ hohi = g_h_hi[(t + 1) & 1];
    float* __restrict__ holo = g_h_lo[(t + 1) & 1];

    const int tid  = threadIdx.x;
    const int lane = tid & 31;
    const int warp = tid >> 5;
    const int mrow = (warp & 1) * 16;
    const int ncol = (warp >> 1) * 16;
    const int g    = lane >> 2, tg = lane & 3;

    auto issue = [&](int it, int s) {
        const int kk = it * 32;
        // segment is uniform per 32-k tile (boundaries 128 and 640 are 32-aligned)
        const float *Shi, *Slo; int ldA, koff;
        if (kk < I_DIM)   { Shi = xhi;      Slo = xlo;      ldA = I_DIM; koff = kk; }
        else if (kk < IH) { Shi = hhi;      Slo = hlo;      ldA = H_DIM; koff = kk - I_DIM; }
        else              { Shi = g_attn_hi; Slo = g_attn_lo; ldA = H_DIM; koff = kk - IH; }
        #pragma unroll
        for (int l = 0; l < 2; l++) {
            int id = tid + l * 128;
            int r = id >> 3, c4 = (id & 7) * 4;
            cp16(&Ah[s][r][c4], Shi + (size_t)(m0 + r) * ldA + koff + c4);
            cp16(&Al[s][r][c4], Slo + (size_t)(m0 + r) * ldA + koff + c4);
        }
        #pragma unroll
        for (int l = 0; l < 2; l++) {
            int id = tid + l * 128;
            int r = id >> 3, c4 = (id & 7) * 4;
            int gn = (r >> 3) * H_DIM + j0 + (r & 7);
            size_t off = (size_t)gn * KC_K + kk + c4;
            cp16(&Bh[s][r][c4], g_Wc_hi + off);
            cp16(&Bl[s][r][c4], g_Wc_lo + off);
        }
        cp_commit();
    };

    float cHH[2][4] = {}, cLH[2][4] = {}, cHL[2][4] = {};

    const int nt = KC_K / 32;  // 36
    issue(0, 0);
    for (int it = 0; it < nt; it++) {
        const int s = it & 1;
        if (it + 1 < nt) { issue(it + 1, s ^ 1); cp_wait1(); }
        else             { cp_wait0(); }
        __syncthreads();

        #pragma unroll
        for (int k8 = 0; k8 < 4; k8++) {
            const int k0 = k8 * 8;
            unsigned ah[4], al[4];
            ah[0] = __float_as_uint(Ah[s][mrow + g][k0 + tg]);
            ah[1] = __float_as_uint(Ah[s][mrow + g + 8][k0 + tg]);
            ah[2] = __float_as_uint(Ah[s][mrow + g][k0 + tg + 4]);
            ah[3] = __float_as_uint(Ah[s][mrow + g + 8][k0 + tg + 4]);
            al[0] = __float_as_uint(Al[s][mrow + g][k0 + tg]);
            al[1] = __float_as_uint(Al[s][mrow + g + 8][k0 + tg]);
            al[2] = __float_as_uint(Al[s][mrow + g][k0 + tg + 4]);
            al[3] = __float_as_uint(Al[s][mrow + g + 8][k0 + tg + 4]);

            #pragma unroll
            for (int ns = 0; ns < 2; ns++) {
                int n = ncol + ns * 8 + g;
                unsigned bh0 = __float_as_uint(Bh[s][n][k0 + tg]);
                unsigned bh1 = __float_as_uint(Bh[s][n][k0 + tg + 4]);
                unsigned bl0 = __float_as_uint(Bl[s][n][k0 + tg]);
                unsigned bl1 = __float_as_uint(Bl[s][n][k0 + tg + 4]);
                mma8(cHH[ns], ah, bh0, bh1);
                mma8(cLH[ns], al, bh0, bh1);
                mma8(cHL[ns], ah, bl0, bl1);
            }
        }
        __syncthreads();
    }

    // exchange preact through smem
    #pragma unroll
    for (int ns = 0; ns < 2; ns++) {
        int col0 = ncol + ns * 8 + 2 * tg;
        sP[mrow + g][col0]         = cHH[ns][0] + cLH[ns][0] + cHL[ns][0];
        sP[mrow + g][col0 + 1]     = cHH[ns][1] + cLH[ns][1] + cHL[ns][1];
        sP[mrow + g + 8][col0]     = cHH[ns][2] + cLH[ns][2] + cHL[ns][2];
        sP[mrow + g + 8][col0 + 1] = cHH[ns][3] + cLH[ns][3] + cHL[ns][3];
    }
    __syncthreads();

    // pointwise: 2 cells per thread (rows tid>>3 and +16? no: 32 rows x 8 j = 256 cells)
    // cells: row = (tid*2)>>3? Use: each thread handles rows r and r+16 at col jj.
    const int row = tid >> 3;          // 0..15
    const int jj  = tid & 7;           // 0..7
    const int j   = j0 + jj;

    float bii = bi[j]             + ba[j];
    float bif = bi[H_DIM + j]     + ba[H_DIM + j];
    float bio = bi[2 * H_DIM + j] + ba[2 * H_DIM + j];
    float big = bi[3 * H_DIM + j] + ba[3 * H_DIM + j];

    #pragma unroll
    for (int half = 0; half < 2; half++) {
        int r = row + half * 16;
        int b = m0 + r;
        float pi = sP[r][jj]      + bii;
        float pf = sP[r][8 + jj]  + bif;
        float po = sP[r][16 + jj] + bio;
        float pg = sP[r][24 + jj] + big;

        float ig = 1.f / (1.f + expf(-pi));
        float fg = 1.f / (1.f + expf(-pf));
        float og = 1.f / (1.f + expf(-po));
        float gg = tanhf(pg);

        size_t idx = (size_t)b * H_DIM + j;
        float cn = g_c[idx] * fg + ig * gg;
        float hn = og * tanhf(cn);

        g_c[idx] = cn;
        split_store(cn, &g_c_hi[idx], &g_c_lo[idx]);
        split_store(hn, &hohi[idx], &holo[idx]);
        out[(size_t)t * B_DIM * H_DIM + idx] = hn;
    }
}

// ---------------- launcher --------------------------------------------------
extern "C" void kernel_launch(void* const* d_in, const int* in_sizes, int n_in,
                              void* d_out, int out_size) {
    const float* x  = (const float*)d_in[0];
    const float* Wi = (const float*)d_in[1];
    const float* bi = (const float*)d_in[2];
    const float* Wh = (const float*)d_in[3];
    const float* Wv = (const float*)d_in[4];
    const float* bv = (const float*)d_in[5];
    const float* Wq = (const float*)d_in[6];
    const float* bq = (const float*)d_in[7];
    const float* Wa = (const float*)d_in[8];
    const float* ba = (const float*)d_in[9];
    float* out = (float*)d_out;

    init_kernel<<<1024, 256>>>(bv);
    prep_x<<<2048, 256>>>(x);
    prep_wc<<<2048, 256>>>(Wi, Wh, Wa);
    prep_wqv<<<1024, 256>>>(Wq, Wv);
    for (int t = 0; t < T_LEN; t++) {
        ka_kernel<<<128, 128>>>(t, bq, bv);
        kb_kernel<<<128, 128>>>(t);
        kc_kernel<<<256, 128>>>(t, bi, ba, out);
    }
}